// round 2
// baseline (speedup 1.0000x reference)
#include <cuda_runtime.h>
#include <cuda_bf16.h>
#include <math.h>

// Problem constants (from reference: NC=1000, K=8, N=32, D=128)
#define G_TOT   8000
#define NPT     32
#define DIM     128
#define RS      132            // padded row stride (floats) for bank-conflict-free float4
#define ITERS   20
#define TOLF    1e-6f
#define EPSF    1e-7f
#define CLIPF   1e-7f

// Scratch (static __device__ — no allocation at runtime)
__device__ float g_vnorm[(size_t)ITERS * G_TOT];
__device__ float g_muhist[(size_t)(ITERS + 1) * G_TOT * DIM];   // 86 MB
__device__ float g_maxv[ITERS];
__device__ int   g_tstar;
__device__ float g_gloss[G_TOT];

__device__ __forceinline__ float warpSum(float v) {
    #pragma unroll
    for (int o = 16; o > 0; o >>= 1)
        v += __shfl_xor_sync(0xffffffffu, v, o);
    return v;
}

// ---------------------------------------------------------------------------
// Kernel 1: per-group Karcher iterations. One warp per group.
// Records vnorm per (iter, g) and mu history per (iter, g).
// ---------------------------------------------------------------------------
__global__ void __launch_bounds__(32) karcher_kernel(const float* __restrict__ X) {
    __shared__ float Xs[NPT * RS];
    __shared__ float mus[DIM];

    const int g = blockIdx.x;
    const int lane = threadIdx.x;
    const float4* __restrict__ Xg = (const float4*)(X + (size_t)g * NPT * DIM);

    // Coalesced staging: 1024 float4s, lane-strided
    #pragma unroll
    for (int i = lane; i < NPT * DIM / 4; i += 32) {
        int n = i >> 5;         // point
        int j = i & 31;         // float4 index in row
        float4 v = Xg[i];
        *(float4*)&Xs[n * RS + 4 * j] = v;
    }
    __syncwarp();

    // Normalize row `lane` (each lane owns one point)
    {
        float* row = &Xs[lane * RS];
        float acc = 0.f;
        #pragma unroll
        for (int j = 0; j < 32; j++) {
            float4 v = *(float4*)&row[4 * j];
            acc += v.x * v.x + v.y * v.y + v.z * v.z + v.w * v.w;
        }
        float inv = 1.f / fmaxf(sqrtf(acc), 1e-12f);
        #pragma unroll
        for (int j = 0; j < 32; j++) {
            float4 v = *(float4*)&row[4 * j];
            v.x *= inv; v.y *= inv; v.z *= inv; v.w *= inv;
            *(float4*)&row[4 * j] = v;
        }
    }
    __syncwarp();

    // Init mu = normalize(mean(Xn)). Lane owns dims [4*lane, 4*lane+3].
    float4 mu4;
    {
        float4 s = make_float4(0.f, 0.f, 0.f, 0.f);
        #pragma unroll
        for (int n = 0; n < NPT; n++) {
            float4 v = *(float4*)&Xs[n * RS + 4 * lane];
            s.x += v.x; s.y += v.y; s.z += v.z; s.w += v.w;
        }
        const float invN = 1.f / 32.f;
        s.x *= invN; s.y *= invN; s.z *= invN; s.w *= invN;
        float q = warpSum(s.x * s.x + s.y * s.y + s.z * s.z + s.w * s.w);
        float inv = 1.f / fmaxf(sqrtf(q), 1e-12f);
        mu4.x = s.x * inv; mu4.y = s.y * inv; mu4.z = s.z * inv; mu4.w = s.w * inv;
        *(float4*)&mus[4 * lane] = mu4;
        ((float4*)&g_muhist[(size_t)g * DIM])[lane] = mu4;
    }
    __syncwarp();

    for (int it = 0; it < ITERS; ++it) {
        // --- dots: lane = point; full D dot with mu (mu broadcast from smem)
        const float* row = &Xs[lane * RS];
        float dot = 0.f;
        #pragma unroll
        for (int j = 0; j < 32; j++) {
            float4 m = *(float4*)&mus[4 * j];
            float4 v = *(float4*)&row[4 * j];
            dot = fmaf(m.x, v.x, fmaf(m.y, v.y, fmaf(m.z, v.z, fmaf(m.w, v.w, dot))));
        }
        // theta from CLIPPED dot; diff uses UNCLIPPED dot (matches reference)
        float dc    = fminf(fmaxf(dot, -1.f + CLIPF), 1.f - CLIPF);
        float theta = acosf(dc);
        float st    = fmaxf(sinf(theta), EPSF);
        float w     = theta / st;

        // c = sum_n w_n * dot_n  (unclipped dot)
        float c = warpSum(w * dot);

        // --- s1[d] = sum_n w_n * Xn[n][d]; lane owns dims 4*lane..4*lane+3
        float4 s1 = make_float4(0.f, 0.f, 0.f, 0.f);
        #pragma unroll
        for (int n = 0; n < NPT; n++) {
            float wn = __shfl_sync(0xffffffffu, w, n);
            float4 v = *(float4*)&Xs[n * RS + 4 * lane];
            s1.x = fmaf(wn, v.x, s1.x);
            s1.y = fmaf(wn, v.y, s1.y);
            s1.z = fmaf(wn, v.z, s1.z);
            s1.w = fmaf(wn, v.w, s1.w);
        }
        const float invN = 1.f / 32.f;
        float4 v4;
        v4.x = (s1.x - c * mu4.x) * invN;
        v4.y = (s1.y - c * mu4.y) * invN;
        v4.z = (s1.z - c * mu4.z) * invN;
        v4.w = (s1.w - c * mu4.w) * invN;

        float vq = warpSum(v4.x * v4.x + v4.y * v4.y + v4.z * v4.z + v4.w * v4.w);
        float vnorm = fmaxf(sqrtf(vq), EPSF);
        if (lane == 0) g_vnorm[(size_t)it * G_TOT + g] = vnorm;

        // exp map (STEP = 1.0 => vs_norm == vnorm)
        float ca = cosf(vnorm);
        float sa = sinf(vnorm);
        float k  = sa / vnorm;
        float4 mn;
        mn.x = fmaf(ca, mu4.x, k * v4.x);
        mn.y = fmaf(ca, mu4.y, k * v4.y);
        mn.z = fmaf(ca, mu4.z, k * v4.z);
        mn.w = fmaf(ca, mu4.w, k * v4.w);
        float mq   = warpSum(mn.x * mn.x + mn.y * mn.y + mn.z * mn.z + mn.w * mn.w);
        float minv = 1.f / fmaxf(sqrtf(mq), 1e-12f);
        mu4.x = mn.x * minv; mu4.y = mn.y * minv; mu4.z = mn.z * minv; mu4.w = mn.w * minv;

        __syncwarp();   // all lanes finished reading old mus
        *(float4*)&mus[4 * lane] = mu4;
        ((float4*)&g_muhist[((size_t)(it + 1) * G_TOT + g) * DIM])[lane] = mu4;
        __syncwarp();   // new mus visible before next dot pass
    }
}

// ---------------------------------------------------------------------------
// Kernel 2: per-iteration max over groups of vnorm
// ---------------------------------------------------------------------------
__global__ void max_kernel() {
    __shared__ float sh[256];
    const int it = blockIdx.x;
    float m = 0.f;
    for (int i = threadIdx.x; i < G_TOT; i += 256)
        m = fmaxf(m, g_vnorm[(size_t)it * G_TOT + i]);
    sh[threadIdx.x] = m;
    __syncthreads();
    for (int s = 128; s > 0; s >>= 1) {
        if (threadIdx.x < s) sh[threadIdx.x] = fmaxf(sh[threadIdx.x], sh[threadIdx.x + s]);
        __syncthreads();
    }
    if (threadIdx.x == 0) g_maxv[it] = sh[0];
}

// ---------------------------------------------------------------------------
// Kernel 3: find t* = first iteration where global max vnorm < TOL (else 20)
// ---------------------------------------------------------------------------
__global__ void tstar_kernel() {
    if (threadIdx.x == 0) {
        int t = ITERS;
        for (int i = 0; i < ITERS; i++) {
            if (g_maxv[i] < TOLF) { t = i; break; }
        }
        g_tstar = t;
    }
}

// ---------------------------------------------------------------------------
// Kernel 4: per-group loss at mu_hist[t*]. One warp per group.
// ---------------------------------------------------------------------------
__global__ void __launch_bounds__(32) loss_kernel(const float* __restrict__ X) {
    __shared__ float Xs[NPT * RS];
    __shared__ float mus[DIM];

    const int g = blockIdx.x;
    const int lane = threadIdx.x;
    const int t = g_tstar;

    // Load selected mu (coalesced)
    *(float4*)&mus[4 * lane] = ((const float4*)&g_muhist[((size_t)t * G_TOT + g) * DIM])[lane];

    // Stage X tile coalesced
    const float4* __restrict__ Xg = (const float4*)(X + (size_t)g * NPT * DIM);
    #pragma unroll
    for (int i = lane; i < NPT * DIM / 4; i += 32) {
        int n = i >> 5, j = i & 31;
        float4 v = Xg[i];
        *(float4*)&Xs[n * RS + 4 * j] = v;
    }
    __syncwarp();

    // Lane = point: sim = (x . mu) / max(||x||, 1e-12), clipped; theta^2
    const float* row = &Xs[lane * RS];
    float dot = 0.f, nn = 0.f;
    #pragma unroll
    for (int j = 0; j < 32; j++) {
        float4 x = *(float4*)&row[4 * j];
        float4 m = *(float4*)&mus[4 * j];
        dot = fmaf(x.x, m.x, fmaf(x.y, m.y, fmaf(x.z, m.z, fmaf(x.w, m.w, dot))));
        nn  = fmaf(x.x, x.x, fmaf(x.y, x.y, fmaf(x.z, x.z, fmaf(x.w, x.w, nn))));
    }
    float inv = 1.f / fmaxf(sqrtf(nn), 1e-12f);
    float sim = dot * inv;
    sim = fminf(fmaxf(sim, -1.f + CLIPF), 1.f - CLIPF);
    float th = acosf(sim);
    float s = warpSum(th * th);
    if (lane == 0) g_gloss[g] = s;
}

// ---------------------------------------------------------------------------
// Kernel 5: deterministic final reduction -> out[0] = mean over groups
// ---------------------------------------------------------------------------
__global__ void reduce_kernel(float* __restrict__ out) {
    __shared__ float sh[256];
    float acc = 0.f;
    for (int i = threadIdx.x; i < G_TOT; i += 256)
        acc += g_gloss[i];
    sh[threadIdx.x] = acc;
    __syncthreads();
    for (int s = 128; s > 0; s >>= 1) {
        if (threadIdx.x < s) sh[threadIdx.x] += sh[threadIdx.x + s];
        __syncthreads();
    }
    if (threadIdx.x == 0) out[0] = sh[0] * (1.f / (float)G_TOT);
}

// ---------------------------------------------------------------------------
extern "C" void kernel_launch(void* const* d_in, const int* in_sizes, int n_in,
                              void* d_out, int out_size) {
    const float* X = (const float*)d_in[0];
    float* out = (float*)d_out;

    karcher_kernel<<<G_TOT, 32>>>(X);
    max_kernel<<<ITERS, 256>>>();
    tstar_kernel<<<1, 32>>>();
    loss_kernel<<<G_TOT, 32>>>(X);
    reduce_kernel<<<1, 256>>>(out);
}

// round 5
// speedup vs baseline: 2.2042x; 2.2042x over previous
#include <cuda_runtime.h>
#include <cuda_bf16.h>
#include <math.h>

// Problem constants: NC=1000, K=8, N=32, D=128  -> G = 8000 groups
#define G_TOT 8000
#define NPT   32
#define DIM   128
#define ITERS 20
#define TOLF  1e-6f
#define EPSF  1e-7f
#define CLIPF 1e-7f

// Static scratch (no runtime allocation)
__device__ float g_vnorm[(size_t)ITERS * G_TOT];
__device__ float g_lossT[(size_t)(ITERS + 1) * G_TOT];
__device__ float g_maxv[ITERS];

using u64 = unsigned long long;

// ---- packed f32x2 helpers (FFMA2 path ptxas never emits from C++) ----
__device__ __forceinline__ u64 pk2(float a, float b) {
    u64 r; asm("mov.b64 %0, {%1,%2};" : "=l"(r) : "f"(a), "f"(b)); return r;
}
__device__ __forceinline__ float2 upk2(u64 v) {
    float2 r; asm("mov.b64 {%0,%1}, %2;" : "=f"(r.x), "=f"(r.y) : "l"(v)); return r;
}
__device__ __forceinline__ u64 ffma2(u64 a, u64 b, u64 c) {
    u64 d; asm("fma.rn.f32x2 %0, %1, %2, %3;" : "=l"(d) : "l"(a), "l"(b), "l"(c)); return d;
}
__device__ __forceinline__ u64 fmul2(u64 a, u64 b) {
    u64 d; asm("mul.rn.f32x2 %0, %1, %2;" : "=l"(d) : "l"(a), "l"(b)); return d;
}
__device__ __forceinline__ u64 fadd2(u64 a, u64 b) {
    u64 d; asm("add.rn.f32x2 %0, %1, %2;" : "=l"(d) : "l"(a), "l"(b)); return d;
}

__device__ __forceinline__ float warpSum(float v) {
    #pragma unroll
    for (int o = 16; o > 0; o >>= 1)
        v += __shfl_xor_sync(0xffffffffu, v, o);
    return v;
}

// Distributed 32-way reduction: on entry each lane holds partial p[n] for all
// 32 points; on exit lane L holds the full sum for point L in p[0].
// 31 shfl + 62 sel + 31 add, fully unrolled.
__device__ __forceinline__ void distReduce32(float (&v)[32], int lane) {
    #pragma unroll
    for (int stage = 16; stage >= 1; stage >>= 1) {
        bool up = (lane & stage) != 0;
        #pragma unroll
        for (int i = 0; i < stage; i++) {
            float send = up ? v[i] : v[i + stage];
            float keep = up ? v[i + stage] : v[i];
            float recv = __shfl_xor_sync(0xffffffffu, send, stage);
            v[i] = keep + recv;
        }
    }
}

// ---------------------------------------------------------------------------
// Kernel 1: fused normalize + 20 Karcher iterations + per-candidate loss.
// One warp per group. X kept in registers, column layout:
// lane L owns dims [4L..4L+3] of every point as 2 packed f32x2 per point.
// Zero shared memory.
// ---------------------------------------------------------------------------
__global__ void __launch_bounds__(32) karcher_kernel(const float* __restrict__ X) {
    const int g    = blockIdx.x;
    const int lane = threadIdx.x;
    const float4* __restrict__ Xg = (const float4*)X + (size_t)g * (NPT * DIM / 4);

    u64 xa[NPT], xb[NPT];   // point n: dims 4L..4L+1 in xa[n], 4L+2..4L+3 in xb[n]
    float p[NPT];

    // Coalesced load (lane-consecutive float4 -> 512B contiguous per instr)
    // plus per-point squared-norm partials.
    #pragma unroll
    for (int n = 0; n < NPT; n++) {
        float4 v = Xg[n * 32 + lane];
        xa[n] = pk2(v.x, v.y);
        xb[n] = pk2(v.z, v.w);
        p[n]  = v.x * v.x + v.y * v.y + v.z * v.z + v.w * v.w;
    }
    distReduce32(p, lane);                       // p[0] = ||x_lane||^2
    float inv = rsqrtf(fmaxf(p[0], 1e-24f));     // == 1/max(||x||,1e-12)
    #pragma unroll
    for (int n = 0; n < NPT; n++) {
        float invn = __shfl_sync(0xffffffffu, inv, n);
        u64 i2 = pk2(invn, invn);
        xa[n] = fmul2(xa[n], i2);
        xb[n] = fmul2(xb[n], i2);
    }

    // mu = normalize(mean(Xn))
    const u64 K32 = pk2(1.0f / 32.0f, 1.0f / 32.0f);
    u64 sa = 0ull, sb = 0ull;
    #pragma unroll
    for (int n = 0; n < NPT; n++) { sa = fadd2(sa, xa[n]); sb = fadd2(sb, xb[n]); }
    sa = fmul2(sa, K32); sb = fmul2(sb, K32);
    {
        float2 A = upk2(sa), B = upk2(sb);
        float q = warpSum(A.x * A.x + A.y * A.y + B.x * B.x + B.y * B.y);
        float mi = rsqrtf(fmaxf(q, 1e-24f));
        u64 m2 = pk2(mi, mi);
        sa = fmul2(sa, m2); sb = fmul2(sb, m2);
    }
    u64 ma = sa, mb = sb;    // current mu (packed, lane-owned dims)

    #pragma unroll 1
    for (int it = 0; it < ITERS; ++it) {
        // ---- dots: partials in registers, distributed-reduce to lane=point
        #pragma unroll
        for (int n = 0; n < NPT; n++) {
            u64 t = ffma2(ma, xa[n], ffma2(mb, xb[n], 0ull));
            float2 tf = upk2(t);
            p[n] = tf.x + tf.y;
        }
        distReduce32(p, lane);
        float dot = p[0];                                     // point `lane`

        float dc    = fminf(fmaxf(dot, -1.0f + CLIPF), 1.0f - CLIPF);
        float theta = acosf(dc);
        float st    = fmaxf(sqrtf(fmaf(-dc, dc, 1.0f)), EPSF); // sin(acos(dc))
        float w     = __fdividef(theta, st);

        float c = warpSum(w * dot);                 // sum_n w_n * dot_n (unclipped)
        float lsum = warpSum(theta * theta);        // loss if frozen at this iter
        if (lane == 0) g_lossT[(size_t)it * G_TOT + g] = lsum;

        // ---- s1[d] = sum_n w_n * x[n][d]
        u64 s1a = 0ull, s1b = 0ull;
        #pragma unroll
        for (int n = 0; n < NPT; n++) {
            float wn = __shfl_sync(0xffffffffu, w, n);
            u64 w2 = pk2(wn, wn);
            s1a = ffma2(w2, xa[n], s1a);
            s1b = ffma2(w2, xb[n], s1b);
        }

        // v = (s1 - c*mu) / 32
        u64 ncc = pk2(-c, -c);
        u64 va = fmul2(ffma2(ncc, ma, s1a), K32);
        u64 vb = fmul2(ffma2(ncc, mb, s1b), K32);
        float2 vA = upk2(va), vB = upk2(vb);
        float vq = warpSum(vA.x * vA.x + vA.y * vA.y + vB.x * vB.x + vB.y * vB.y);
        float vnorm = fmaxf(sqrtf(vq), EPSF);
        if (lane == 0) g_vnorm[(size_t)it * G_TOT + g] = vnorm;

        // exp map + renormalize (STEP = 1)
        float ca = __cosf(vnorm);
        float sa_ = __sinf(vnorm);
        float kk = __fdividef(sa_, vnorm);
        u64 ca2 = pk2(ca, ca), kk2 = pk2(kk, kk);
        u64 na = ffma2(ca2, ma, fmul2(kk2, va));
        u64 nb = ffma2(ca2, mb, fmul2(kk2, vb));
        float2 nA = upk2(na), nB = upk2(nb);
        float mq = warpSum(nA.x * nA.x + nA.y * nA.y + nB.x * nB.x + nB.y * nB.y);
        float mi = rsqrtf(fmaxf(mq, 1e-24f));
        u64 mi2 = pk2(mi, mi);
        ma = fmul2(na, mi2); mb = fmul2(nb, mi2);
    }

    // ---- loss candidate t = 20 (no freeze): dots with final mu
    #pragma unroll
    for (int n = 0; n < NPT; n++) {
        u64 t = ffma2(ma, xa[n], ffma2(mb, xb[n], 0ull));
        float2 tf = upk2(t);
        p[n] = tf.x + tf.y;
    }
    distReduce32(p, lane);
    float dc = fminf(fmaxf(p[0], -1.0f + CLIPF), 1.0f - CLIPF);
    float th = acosf(dc);
    float ls = warpSum(th * th);
    if (lane == 0) g_lossT[(size_t)ITERS * G_TOT + g] = ls;
}

// ---------------------------------------------------------------------------
// Kernel 2: per-iteration max over groups of vnorm
// ---------------------------------------------------------------------------
__global__ void max_kernel() {
    __shared__ float sh[256];
    const int it = blockIdx.x;
    float m = 0.f;
    for (int i = threadIdx.x; i < G_TOT; i += 256)
        m = fmaxf(m, g_vnorm[(size_t)it * G_TOT + i]);
    sh[threadIdx.x] = m;
    __syncthreads();
    for (int s = 128; s > 0; s >>= 1) {
        if (threadIdx.x < s) sh[threadIdx.x] = fmaxf(sh[threadIdx.x], sh[threadIdx.x + s]);
        __syncthreads();
    }
    if (threadIdx.x == 0) g_maxv[it] = sh[0];
}

// ---------------------------------------------------------------------------
// Kernel 3: t* selection + deterministic mean of the selected losses
// ---------------------------------------------------------------------------
__global__ void final_kernel(float* __restrict__ out) {
    __shared__ float sh[1024];
    __shared__ int ts;
    if (threadIdx.x == 0) {
        int t = ITERS;
        for (int i = 0; i < ITERS; i++)
            if (g_maxv[i] < TOLF) { t = i; break; }
        ts = t;
    }
    __syncthreads();
    const int t = ts;
    float acc = 0.f;
    for (int i = threadIdx.x; i < G_TOT; i += 1024)
        acc += g_lossT[(size_t)t * G_TOT + i];
    sh[threadIdx.x] = acc;
    __syncthreads();
    for (int s = 512; s > 0; s >>= 1) {
        if (threadIdx.x < s) sh[threadIdx.x] += sh[threadIdx.x + s];
        __syncthreads();
    }
    if (threadIdx.x == 0) out[0] = sh[0] * (1.0f / (float)G_TOT);
}

// ---------------------------------------------------------------------------
extern "C" void kernel_launch(void* const* d_in, const int* in_sizes, int n_in,
                              void* d_out, int out_size) {
    const float* X = (const float*)d_in[0];
    float* out = (float*)d_out;

    karcher_kernel<<<G_TOT, 32>>>(X);
    max_kernel<<<ITERS, 256>>>();
    final_kernel<<<1, 1024>>>(out);
}